// round 3
// baseline (speedup 1.0000x reference)
#include <cuda_runtime.h>
#include <cuda_bf16.h>
#include <cstdint>

// MX (block-32, E8M0 scale, E4M3 elements) quantize-dequantize.
// One float4 per lane; warp = 128 floats = 4 MX blocks; block = 8 lanes.

__device__ __forceinline__ float exp2i(int k) {
    // exact 2^k for k in [-126, 127]
    return __uint_as_float((unsigned)(k + 127) << 23);
}

__device__ __forceinline__ float qdq_e4m3(float x, float inv_scale, float scale) {
    float v = x * inv_scale;                 // exact: inv_scale is a power of two
    float mag = fminf(fabsf(v), 448.0f);     // saturate to E4M3 max
    float safe = fmaxf(mag, 0.015625f);      // 2^-6: subnormal region shares emin quantum
    int e = (int)((__float_as_uint(safe) >> 23) & 0xFF) - 127;   // exact floor(log2(safe))
    // quantum = 2^(e-3); RNE via rintf
    float q = rintf(mag * exp2i(3 - e)) * exp2i(e - 3);
    return copysignf(q, v) * scale;
}

__global__ void __launch_bounds__(256) mx_qdq_kernel(const float4* __restrict__ in,
                                                     float4* __restrict__ out,
                                                     int n4) {
    int i = blockIdx.x * blockDim.x + threadIdx.x;
    if (i >= n4) return;

    float4 v = in[i];

    float amax = fmaxf(fmaxf(fabsf(v.x), fabsf(v.y)),
                       fmaxf(fabsf(v.z), fabsf(v.w)));
    // reduce over the 8 lanes forming one 32-element MX block
    amax = fmaxf(amax, __shfl_xor_sync(0xFFFFFFFFu, amax, 1));
    amax = fmaxf(amax, __shfl_xor_sync(0xFFFFFFFFu, amax, 2));
    amax = fmaxf(amax, __shfl_xor_sync(0xFFFFFFFFu, amax, 4));

    float scale, inv_scale;
    if (amax > 0.0f) {
        int ea = (int)((__float_as_uint(amax) >> 23) & 0xFF) - 127; // floor(log2(amax)) (normal)
        int se = ea - 8;                                            // ELEM_EMAX = 8
        se = max(-127, min(127, se));                               // E8M0 clip
        if (se > -127) {
            scale     = exp2i(se);
            inv_scale = exp2i(-se);
        } else {
            scale     = __uint_as_float(0x00400000u);               // 2^-127 (subnormal)
            inv_scale = exp2i(127);
        }
    } else {
        scale = 1.0f;
        inv_scale = 1.0f;
    }

    float4 o;
    o.x = qdq_e4m3(v.x, inv_scale, scale);
    o.y = qdq_e4m3(v.y, inv_scale, scale);
    o.z = qdq_e4m3(v.z, inv_scale, scale);
    o.w = qdq_e4m3(v.w, inv_scale, scale);
    out[i] = o;
}

extern "C" void kernel_launch(void* const* d_in, const int* in_sizes, int n_in,
                              void* d_out, int out_size) {
    const float* x = (const float*)d_in[0];
    float* out = (float*)d_out;
    int n = in_sizes[0];            // 4096*8192, multiple of 128
    int n4 = n / 4;
    int threads = 256;
    int blocks = (n4 + threads - 1) / threads;
    mx_qdq_kernel<<<blocks, threads>>>((const float4*)x, (float4*)out, n4);
}